// round 17
// baseline (speedup 1.0000x reference)
#include <cuda_runtime.h>
#include <float.h>

// Blocked CYK inside-outside in ONE launch.
// B=8, S=256. Grid = 64 CTAs = 8 clusters (one per batch) x 8 CTAs x 1024 thr.
// 8x8 tiles, 32 tile-diagonals per pass -> 64 cluster syncs total (vs 509
// fine-grained). Intra-tile deps resolved with __syncthreads (cheap); each CTA
// processes up to 4 tiles concurrently in separate smem slots.
//
// Inside (log space):  A[i,j] = s[i,j] + LSE_{i<k<j}(A[i,k]+A[k,j]),  L = A - s
// Outside (prob space, gather; exponents <= 0):
//   mu[p,q] = [root] + sum_{b>q} mu[p,b]*exp(A[p,q]+A[q,b]-L[p,b])
//                    + sum_{a<p} mu[a,q]*exp(A[a,p]+A[p,q]-L[a,q])
// Deterministic, atomic-free.

constexpr int Bb = 8;
constexpr int Ss = 256;
constexpr int NN = Ss * Ss;
constexpr int NT = 1024;
constexpr int CPC = 8;     // CTAs per cluster
constexpr int NTILE = 32;  // 256/8 tiles per side
constexpr int SLOTS = 4;   // max tiles per CTA per diagonal

__device__ float g_A  [Bb * NN];
__device__ float g_AT [Bb * NN];
__device__ float g_L  [Bb * NN];
__device__ float g_LT [Bb * NN];
__device__ float g_mu [Bb * NN];
__device__ float g_muT[Bb * NN];

__device__ __forceinline__ void cluster_sync() {
    asm volatile("barrier.cluster.arrive.aligned;" ::: "memory");
    asm volatile("barrier.cluster.wait.aligned;" ::: "memory");
}
__device__ __forceinline__ float warpMax(float v) {
#pragma unroll
    for (int o = 16; o; o >>= 1) v = fmaxf(v, __shfl_xor_sync(0xffffffffu, v, o));
    return v;
}
__device__ __forceinline__ float warpSum(float v) {
#pragma unroll
    for (int o = 16; o; o >>= 1) v += __shfl_xor_sync(0xffffffffu, v, o);
    return v;
}
__device__ __forceinline__ void lse_update(float v, float& mx, float& s) {
    float nm = fmaxf(mx, v);
    s = s * __expf(mx - nm) + __expf(v - nm);
    mx = nm;
}

// smem slot arrays: 0 = X0 (sII / sAQQ), 1 = X1 (sJJ / sAPP),
// 2 = SC (scores / A-current), 3 = CUR (scur / smuc),
// 4 = M (bulk max / bulk acc), 5 = S (bulk sum / L-current)
__global__ __cluster_dims__(CPC, 1, 1) __launch_bounds__(NT, 1)
void crf_kernel(const float* __restrict__ scores, float* __restrict__ out) {
    const int b    = blockIdx.x / CPC;
    const int rank = blockIdx.x % CPC;
    const int tid  = threadIdx.x;
    const int lane = tid & 31;
    const int warp = tid >> 5;

    const float* sc = scores + b * NN;
    float* A   = g_A   + b * NN;  float* AT  = g_AT  + b * NN;
    float* L   = g_L   + b * NN;  float* LT  = g_LT  + b * NN;
    float* mu  = g_mu  + b * NN;  float* muT = g_muT + b * NN;
    float* o   = out   + b * NN;

    __shared__ float sm[SLOTS][6][8][9];

    // sweep-thread identity (tid < 256): slot, local cell
    const bool is_sw = (tid < 256);
    const int t_s  = (tid >> 6) & 3;
    const int cel  = tid & 63;
    const int il   = cel >> 3, jl = cel & 7;

    // ── init: zero lower triangle + diagonal of out ──
    for (int idx = rank * NT + tid; idx < NN; idx += CPC * NT) {
        int i = idx >> 8, j = idx & 255;
        if (j <= i) o[idx] = 0.f;
    }

    // ── inside d=0: diagonal tiles, 4 per CTA (I = rank*4 + slot) ──
    {
        const int I = rank * 4 + t_s, Ib = I * 8;
        if (is_sw)
            sm[t_s][2][il][jl] = sc[(Ib + il) * Ss + Ib + jl];
        __syncthreads();
        float r = 0.f;
        for (int w = 1; w <= 7; w++) {
            if (is_sw && jl - il == w) {
                if (w == 1) r = sm[t_s][2][il][jl];
                else {
                    float m = -FLT_MAX, s = 0.f;
                    for (int k = il + 1; k < jl; k++)
                        lse_update(sm[t_s][3][il][k] + sm[t_s][3][k][jl], m, s);
                    r = sm[t_s][2][il][jl] + m + __logf(s);
                }
                sm[t_s][3][il][jl] = r;
            }
            __syncthreads();
        }
        if (is_sw && jl > il) {
            int gi = Ib + il, gj = Ib + jl;
            A [gi * Ss + gj] = r;  AT[gj * Ss + gi] = r;
            float lv = r - sm[t_s][2][il][jl];
            L [gi * Ss + gj] = lv; LT[gj * Ss + gi] = lv;
        }
    }
    cluster_sync();

    // ── inside d=1..31 ──
    for (int d = 1; d < NTILE; d++) {
        const int ntiles = NTILE - d;
        const int Tsw = rank + CPC * t_s;
        const bool sw = is_sw && Tsw < ntiles;
        if (sw) {
            int I = Tsw, J = I + d, Ib = I * 8, Jb = J * 8;
            sm[t_s][0][il][jl] = A[(Ib + il) * Ss + Ib + jl];   // sII
            sm[t_s][1][il][jl] = A[(Jb + il) * Ss + Jb + jl];   // sJJ
            sm[t_s][2][il][jl] = sc[(Ib + il) * Ss + Jb + jl];  // scores
        }
        // bulk: warp -> slot warp>>3, 8 cells each; lane-strided middle-k LSE
        {
            const int t_b = warp >> 3;
            const int Tb = rank + CPC * t_b;
            if (Tb < ntiles) {
                int I = Tb, J = I + d, Ib = I * 8, Jb = J * 8;
                const int n = 8 * (d - 1);
                const int cbase = (warp & 7) * 8;
                for (int cc = 0; cc < 8; cc++) {
                    int cell = cbase + cc, cil = cell >> 3, cjl = cell & 7;
                    const float* Ar = A  + (Ib + cil) * Ss + 8 * (I + 1);
                    const float* Br = AT + (Jb + cjl) * Ss + 8 * (I + 1);
                    float m0 = -FLT_MAX, s0 = 0.f, m1 = -FLT_MAX, s1 = 0.f;
                    for (int k = lane; k < n; k += 64) {
                        lse_update(Ar[k] + Br[k], m0, s0);
                        int k2 = k + 32;
                        if (k2 < n) lse_update(Ar[k2] + Br[k2], m1, s1);
                    }
                    // merge the two accumulators (empty ones contribute 0)
                    float nm = fmaxf(m0, m1);
                    float sl = s0 * __expf(m0 - nm) + s1 * __expf(m1 - nm);
                    float M = warpMax(nm);
                    sl = sl * __expf(nm - M);
                    sl = warpSum(sl);
                    if (lane == 0) { sm[t_b][4][cil][cjl] = M; sm[t_b][5][cil][cjl] = sl; }
                }
            }
        }
        __syncthreads();
        // intra-tile sweep: 15 micro-diagonals
        float r = 0.f;
        for (int md = 0; md < 15; md++) {
            if (sw && (7 - il) + jl == md) {
                float m = sm[t_s][4][il][jl], s = sm[t_s][5][il][jl];
                // pass 1: max
                float vmax = m;
                for (int k = il + 1; k < 8; k++)
                    vmax = fmaxf(vmax, sm[t_s][0][il][k] + sm[t_s][3][k][jl]);
                for (int k = 0; k < jl; k++)
                    vmax = fmaxf(vmax, sm[t_s][3][il][k] + sm[t_s][1][k][jl]);
                // pass 2: exp-sum (s==0 & m=-FLT_MAX -> contributes 0)
                float acc = s * __expf(m - vmax);
                for (int k = il + 1; k < 8; k++)
                    acc += __expf(sm[t_s][0][il][k] + sm[t_s][3][k][jl] - vmax);
                for (int k = 0; k < jl; k++)
                    acc += __expf(sm[t_s][3][il][k] + sm[t_s][1][k][jl] - vmax);
                float scv = sm[t_s][2][il][jl];
                if (d == 1 && il == 7 && jl == 0) r = scv;        // width-1 span
                else r = scv + vmax + __logf(acc);
                sm[t_s][3][il][jl] = r;
            }
            __syncthreads();
        }
        if (sw) {
            int I = Tsw, J = I + d;
            int gi = I * 8 + il, gj = J * 8 + jl;
            A [gi * Ss + gj] = r;  AT[gj * Ss + gi] = r;
            float lv = r - sm[t_s][2][il][jl];
            L [gi * Ss + gj] = lv; LT[gj * Ss + gi] = lv;
        }
        cluster_sync();
    }

    // ── outside d=31..0 ──
    for (int d = NTILE - 1; d >= 0; d--) {
        const int ntiles = NTILE - d;
        const int Tsw = rank + CPC * t_s;
        const bool sw = is_sw && Tsw < ntiles;
        if (sw) {
            int P = Tsw, Q = P + d, Pb = P * 8, Qb = Q * 8;
            sm[t_s][0][il][jl] = A[(Qb + il) * Ss + Qb + jl];  // sAQQ
            sm[t_s][1][il][jl] = A[(Pb + il) * Ss + Pb + jl];  // sAPP
            sm[t_s][2][il][jl] = A[(Pb + il) * Ss + Qb + jl];  // A current
            sm[t_s][5][il][jl] = L[(Pb + il) * Ss + Qb + jl];  // L current
            sm[t_s][3][il][jl] = 0.f;                          // smuc
        }
        // bulk exterior parents
        {
            const int t_b = warp >> 3;
            const int Tb = rank + CPC * t_b;
            if (Tb < ntiles) {
                int P = Tb, Q = P + d, Pb = P * 8, Qb = Q * 8;
                const int cbase = (warp & 7) * 8;
                for (int cc = 0; cc < 8; cc++) {
                    int cell = cbase + cc, cpl = cell >> 3, cql = cell & 7;
                    int p = Pb + cpl, q = Qb + cql;
                    float acc = 0.f;
                    if (q > p) {
                        float apq = A[p * Ss + q];
                        const int n1 = Ss - 8 * (Q + 1);
                        const float* M1 = mu + p * Ss + 8 * (Q + 1);
                        const float* X1 = A  + q * Ss + 8 * (Q + 1);
                        const float* Y1 = L  + p * Ss + 8 * (Q + 1);
#pragma unroll 2
                        for (int k = lane; k < n1; k += 32)
                            acc += M1[k] * __expf(apq + X1[k] - Y1[k]);
                        const int n2 = 8 * P;
                        const float* M2 = muT + q * Ss;
                        const float* X2 = AT  + p * Ss;
                        const float* Y2 = LT  + q * Ss;
#pragma unroll 2
                        for (int k = lane; k < n2; k += 32)
                            acc += M2[k] * __expf(X2[k] + apq - Y2[k]);
                    }
                    acc = warpSum(acc);
                    if (lane == 0) sm[t_b][4][cpl][cql] = acc;
                }
            }
        }
        __syncthreads();
        // intra-tile sweep (parents within tile row Q / tile col P)
        float muv = 0.f;
        for (int md = 0; md < 15; md++) {
            if (sw && il + (7 - jl) == md) {
                int P = Tsw, Q = P + d;
                int p = P * 8 + il, q = Q * 8 + jl;
                if (q > p) {
                    float acc = sm[t_s][4][il][jl];
                    float apq = sm[t_s][2][il][jl];
                    for (int k = jl + 1; k < 8; k++)
                        acc += sm[t_s][3][il][k] *
                               __expf(apq + sm[t_s][0][jl][k] - sm[t_s][5][il][k]);
                    for (int k = 0; k < il; k++)
                        acc += sm[t_s][3][k][jl] *
                               __expf(sm[t_s][1][k][il] + apq - sm[t_s][5][k][jl]);
                    if (p == 0 && q == Ss - 1) acc += 1.f;  // root
                    muv = acc;
                    sm[t_s][3][il][jl] = muv;
                }
            }
            __syncthreads();
        }
        if (sw) {
            int P = Tsw, Q = P + d;
            int p = P * 8 + il, q = Q * 8 + jl;
            if (q > p) {
                mu [p * Ss + q] = muv;
                muT[q * Ss + p] = muv;
                o  [p * Ss + q] = muv;
            }
        }
        cluster_sync();
    }
}

extern "C" void kernel_launch(void* const* d_in, const int* in_sizes, int n_in,
                              void* d_out, int out_size) {
    const float* scores = (const float*)d_in[0];
    float* out = (float*)d_out;
    crf_kernel<<<Bb * CPC, NT>>>(scores, out);
}